// round 10
// baseline (speedup 1.0000x reference)
#include <cuda_runtime.h>
#include <cuda_fp16.h>
#include <cstdint>

#define DINLINE __device__ __forceinline__

static constexpr int Bd = 2048;
static constexpr int Hd = 256;
static constexpr int Td = 512;
static constexpr int MT = 64;                  // batch tile rows (per tile)
static constexpr int NT = 128;                 // gate-column tile
static constexpr int NGRP = Bd / MT;           // 32 M-groups (barrier groups)
static constexpr int NSLC = (4 * Hd) / NT;     // 8 N-slices
static constexpr int GRID = 128;               // each CTA owns 2 M-tiles x 1 slice
static constexpr int NTHR = 256;               // 8 warps: 2 (M) x 4 (N), 32x32 warp tiles

// SMEM layout (dynamic)
static constexpr int SM_BIAS = 0;              // 128 floats (float4 per hidden unit: i,f,g,o)
static constexpr int SM_A0 = 1024;             // h tile0 [64][256] f16 swizzled (32KB)
static constexpr int SM_A1 = SM_A0 + 32768;    // h tile1 (32KB)
static constexpr int SM_W = SM_A0 + 65536;     // W tile [128 n][256 k] f16 swizzled (64KB)
static constexpr int SM_TOTAL = SM_W + 65536;  // 132096 B

// ---------------- device globals (scratch; no allocations) ----------------
__device__ __align__(16) __half g_hbuf[2][Bd * Hd];                  // ping-pong h (fp16)
__device__ __align__(1024) unsigned char g_Wimg[2][NSLC][65536];     // [W_ih, W_ih+W_hh] smem images
__device__ float g_bias[NSLC][NT];
__device__ unsigned int g_cnt[NGRP];
__device__ int g_gen[NGRP];

// ---------------- helpers ----------------
DINLINE uint32_t smem_u32(const void* p) {
    uint32_t a;
    asm("{ .reg .u64 t; cvta.to.shared.u64 t, %1; cvt.u32.u64 %0, t; }" : "=r"(a) : "l"(p));
    return a;
}
DINLINE void cp16(uint32_t s, const void* g) {
    asm volatile("cp.async.cg.shared.global [%0], [%1], 16;" :: "r"(s), "l"(g));
}
DINLINE void cp_commit() { asm volatile("cp.async.commit_group;" ::: "memory"); }
DINLINE void cp_wait0()  { asm volatile("cp.async.wait_group 0;" ::: "memory"); }
DINLINE void cp_wait1()  { asm volatile("cp.async.wait_group 1;" ::: "memory"); }
DINLINE void cp_wait2()  { asm volatile("cp.async.wait_group 2;" ::: "memory"); }

DINLINE void ldsm4(uint32_t* r, uint32_t addr) {
    asm volatile("ldmatrix.sync.aligned.m8n8.x4.shared.b16 {%0,%1,%2,%3}, [%4];"
                 : "=r"(r[0]), "=r"(r[1]), "=r"(r[2]), "=r"(r[3]) : "r"(addr));
}
DINLINE void mma16816(float* c, const uint32_t* a, uint32_t b0, uint32_t b1) {
    asm volatile(
        "mma.sync.aligned.m16n8k16.row.col.f32.f16.f16.f32 "
        "{%0,%1,%2,%3},{%4,%5,%6,%7},{%8,%9},{%0,%1,%2,%3};"
        : "+f"(c[0]), "+f"(c[1]), "+f"(c[2]), "+f"(c[3])
        : "r"(a[0]), "r"(a[1]), "r"(a[2]), "r"(a[3]), "r"(b0), "r"(b1));
}

// sigmoid via single-MUFU tanh.approx; tanh (feeds h directly) stays EX2+RCP precise
DINLINE float fsig(float x) {
    float t;
    asm("tanh.approx.f32 %0, %1;" : "=f"(t) : "f"(0.5f * x));
    return fmaf(0.5f, t, 0.5f);
}
DINLINE float ftanh(float x) {
    float e, r;
    asm("ex2.approx.f32 %0, %1;" : "=f"(e) : "f"(2.8853900817779268f * x));
    asm("rcp.approx.f32 %0, %1;" : "=f"(r) : "f"(1.0f + e));
    return fmaf(-2.0f, r, 1.0f);
}

// group barrier (R2-proven): last of 8 arrivals publishes generation t+1
DINLINE void grp_release(int mg, int t) {
    unsigned old;
    asm volatile("atom.acq_rel.gpu.global.add.u32 %0, [%1], %2;"
                 : "=r"(old) : "l"(&g_cnt[mg]), "r"(1u) : "memory");
    if (old == (unsigned)(8 * (t + 1) - 1)) {
        asm volatile("st.release.gpu.global.b32 [%0], %1;" :: "l"(&g_gen[mg]), "r"(t + 1) : "memory");
    }
}
DINLINE void grp_wait(int mg, int target) {
    int v;
    do {
        asm volatile("ld.acquire.gpu.global.b32 %0, [%1];" : "=r"(v) : "l"(&g_gen[mg]) : "memory");
        if (v < target) __nanosleep(32);
    } while (v < target);
}

// ---------------- prologue: permuted/swizzled fp16 W images, bias, x->fp16 ----------------
// Column permutation within a 128-col slice: 16-col groups; w=n&15:
//   w<8:  gates (i,f)  unit = 4*(n>>4) + (w>>1), gate = w&1
//   w>=8: gates (g,o)  unit = 4*(n>>4) + ((w-8)>>1), gate = 2 + (w&1)
// -> MMA thread owning cols {2c,2c+1} of n8-tiles (2p, 2p+1) gets all 4 gates of one unit.
__global__ void prep_kernel(const float* __restrict__ x,
                            const float* __restrict__ Wih, const float* __restrict__ Whh,
                            const float* __restrict__ bih, const float* __restrict__ bhh) {
    int g = blockIdx.x * blockDim.x + threadIdx.x;
    if (g < Bd * Hd) g_hbuf[0][g] = __float2half_rn(x[g]);
    if (g < 2 * NSLC * NT * Hd) {  // 524288 entries
        int set = g >> 18;
        int r = g & 262143;
        int j = r >> 15;
        int n = (r >> 8) & 127;
        int k = r & 255;
        int w = n & 15;
        int gate = 2 * (w >> 3) + (w & 1);
        int hl = (n >> 4) * 4 + ((w >> 1) & 3);
        int row = gate * Hd + j * 32 + hl;            // original W row in (4H,H)
        float wv = Wih[row * Hd + k];
        if (set) wv += Whh[row * Hd + k];
        uint32_t byte = (uint32_t)(n * 512 + (((k >> 3) ^ (n & 7)) << 4) + (k & 7) * 2);
        *reinterpret_cast<__half*>(&g_Wimg[set][j][byte]) = __float2half_rn(wv);
    }
    if (g < NSLC * NT) {           // bias as float4 (i,f,g,o) per unit: n = unit*4+gate
        int j = g >> 7, n = g & 127;
        int gate = n & 3, hl = n >> 2;
        int row = gate * Hd + j * 32 + hl;
        g_bias[j][n] = bih[row] + bhh[row];
    }
    if (g < NGRP) { g_cnt[g] = 0; g_gen[g] = 0; }
}

// ---------------- main persistent kernel ----------------
__global__ void __launch_bounds__(NTHR, 1) lstm_kernel(float* __restrict__ out) {
    extern __shared__ __align__(1024) char smem[];
    const uint32_t sb = smem_u32(smem);
    const int tid = threadIdx.x, wid = tid >> 5, lane = tid & 31;
    const int sj = blockIdx.x & 7, cm = blockIdx.x >> 3;
    const int mg0 = cm * 2, mg1 = cm * 2 + 1;
    const int wm = wid >> 2, wn = wid & 3;    // warp tile: rows wm*32, cols wn*32

    if (tid < 32)
        reinterpret_cast<float4*>(smem + SM_BIAS)[tid] = reinterpret_cast<const float4*>(g_bias[sj])[tid];
    {   // group W: load W_ih image (B source at t=0)
        const unsigned char* src = g_Wimg[0][sj];
        #pragma unroll
        for (int i = 0; i < 16; i++) { int q = tid + NTHR * i; cp16(sb + SM_W + q * 16, src + q * 16); }
        cp_commit();
    }

    // A-tile cp.async mapping: 256 threads, row=tid>>2 (0..63), 8 chunks each
    const int am = tid >> 2, acb = tid & 3, amsw = am & 7;
    const uint32_t sA_row = (uint32_t)(am * 512);
    const uint32_t gA_row = (uint32_t)(am * Hd);
    {   // groups A0, A1: initial h tiles from g_hbuf[0]
        const __half* h0 = g_hbuf[0] + (size_t)mg0 * MT * Hd;
        #pragma unroll
        for (int i = 0; i < 8; i++) { int ch = acb + 4 * i; cp16(sb + SM_A0 + sA_row + (uint32_t)((ch ^ amsw) << 4), h0 + gA_row + ch * 8); }
        cp_commit();
        const __half* h1 = g_hbuf[0] + (size_t)mg1 * MT * Hd;
        #pragma unroll
        for (int i = 0; i < 8; i++) { int ch = acb + 4 * i; cp16(sb + SM_A1 + sA_row + (uint32_t)((ch ^ amsw) << 4), h1 + gA_row + ch * 8); }
        cp_commit();
    }

    // ldmatrix per-lane address bases (tile0; tile1 = +32768)
    const int a_row_off = (lane & 7) + (((lane >> 3) & 1) << 3);
    const int a_ch_off  = (lane >> 4) & 1;
    uint32_t a_base[2]; int a_rsw[2];
    #pragma unroll
    for (int mt = 0; mt < 2; mt++) {
        int row = wm * 32 + mt * 16 + a_row_off;
        a_base[mt] = sb + SM_A0 + row * 512;
        a_rsw[mt] = row & 7;
    }
    const int b_ch_off = (lane >> 3) & 1;
    uint32_t b_base[2]; int b_rsw[2];
    #pragma unroll
    for (int np = 0; np < 2; np++) {
        int nrow = wn * 32 + np * 16 + (lane & 7) + (((lane >> 4) & 1) << 3);
        b_base[np] = sb + SM_W + nrow * 512;
        b_rsw[np] = nrow & 7;
    }

    // ---- B fragments resident in registers: breg[kt][np*4 + q] ----
    uint32_t breg[16][8];
    cp_wait2();          // W group done (A0/A1 may still be in flight)
    __syncthreads();
    #pragma unroll
    for (int kt = 0; kt < 16; kt++)
        #pragma unroll
        for (int np = 0; np < 2; np++)
            ldsm4(&breg[kt][np * 4], b_base[np] + (((2 * kt + b_ch_off) ^ b_rsw[np]) << 4));

    // epilogue geometry: thread owns rows r0,r0+8 (x2 mt), units (2wn+up)*4 + (lane&3)
    const int r_lane = lane >> 2, u_lane = lane & 3;
    size_t idxb[2];
    #pragma unroll
    for (int tau = 0; tau < 2; tau++)
        idxb[tau] = (size_t)((cm * 2 + tau) * MT + wm * 32 + r_lane) * Hd + sj * 32;

    float cst[2][8];
    #pragma unroll
    for (int tau = 0; tau < 2; tau++)
        #pragma unroll
        for (int i = 0; i < 8; i++) cst[tau][i] = 0.f;

    const float4* bias4 = reinterpret_cast<const float4*>(smem + SM_BIAS);

    #pragma unroll 1
    for (int t = 0; t < Td; t++) {
        const int cur = t & 1;
        const int oidx = (t == 0) ? 0 : (Td - t);   // x_hat[0]=h0, x_hat[k]=h_{T-k}

        if (t == 1) {   // W_sum image landed (drained below by cp_wait1 at t=1): refresh B regs
            // NOTE: at this point pending groups are [Wsum, A0', A1']; wait until <=1 left
            cp_wait1();
            __syncthreads();
            #pragma unroll
            for (int kt = 0; kt < 16; kt++)
                #pragma unroll
                for (int np = 0; np < 2; np++)
                    ldsm4(&breg[kt][np * 4], b_base[np] + (((2 * kt + b_ch_off) ^ b_rsw[np]) << 4));
        }

        #pragma unroll 1
        for (int tau = 0; tau < 2; tau++) {
            // ---- wait A tile ready, then MMA full-K (A ldsm only; B from regs) ----
            if (tau == 0) cp_wait1(); else cp_wait0();
            __syncthreads();
            float acc[32];
            #pragma unroll
            for (int i = 0; i < 32; i++) acc[i] = 0.f;
            const uint32_t aoff = (uint32_t)(tau * 32768);
            #pragma unroll
            for (int kt = 0; kt < 16; kt++) {
                uint32_t af[2][4];
                #pragma unroll
                for (int mt = 0; mt < 2; mt++)
                    ldsm4(af[mt], a_base[mt] + aoff + (((2 * kt + a_ch_off) ^ a_rsw[mt]) << 4));
                #pragma unroll
                for (int mt = 0; mt < 2; mt++)
                    #pragma unroll
                    for (int nt = 0; nt < 4; nt++)
                        mma16816(&acc[(mt * 4 + nt) * 4], af[mt],
                                 breg[kt][(nt >> 1) * 4 + (nt & 1) * 2],
                                 breg[kt][(nt >> 1) * 4 + (nt & 1) * 2 + 1]);
            }

            // ---- epilogue: all 4 gates per thread, activations, h + x_hat stores ----
            __half* hp = &g_hbuf[cur ^ 1][idxb[tau]];
            float* xp = out + (size_t)oidx * (Bd * Hd) + idxb[tau];
            #pragma unroll
            for (int mt = 0; mt < 2; mt++) {
                #pragma unroll
                for (int up = 0; up < 2; up++) {
                    const float* aI = &acc[(mt * 4 + 2 * up) * 4];       // (i,f) rows r0, r0+8
                    const float* aG = &acc[(mt * 4 + 2 * up + 1) * 4];   // (g,o) rows r0, r0+8
                    const int unit = (2 * wn + up) * 4 + u_lane;
                    float4 bb = bias4[unit];
                    #pragma unroll
                    for (int rh = 0; rh < 2; rh++) {
                        float iv = fsig(aI[2 * rh + 0] + bb.x);
                        float fv = fsig(aI[2 * rh + 1] + bb.y);
                        float gv = ftanh(aG[2 * rh + 0] + bb.z);
                        float ov = fsig(aG[2 * rh + 1] + bb.w);
                        const int li = mt * 4 + up * 2 + rh;
                        float cn = fmaf(fv, cst[tau][li], iv * gv);
                        cst[tau][li] = cn;
                        float hv = ov * ftanh(cn);
                        const size_t off = (size_t)(mt * 16 + rh * 8) * Hd + unit;
                        hp[off] = __float2half_rn(hv);
                        xp[off] = hv;
                        if (t == Td - 1) {
                            float* hfp = out + (size_t)Td * Bd * Hd + idxb[tau];
                            hfp[off] = hv;
                            hfp[(size_t)Bd * Hd + off] = cn;
                        }
                    }
                }
            }
            __syncthreads();   // all h stores of this CTA issued & ordered before release
            if (tid == 0) grp_release(tau == 0 ? mg0 : mg1, t);

            // W-swap after tile1's MMA at t==0 (own cp.async group; drained at t==1)
            if (t == 0 && tau == 1) {
                const unsigned char* src = g_Wimg[1][sj];
                #pragma unroll
                for (int i = 0; i < 16; i++) { int q = tid + NTHR * i; cp16(sb + SM_W + q * 16, src + q * 16); }
                cp_commit();
            }
        }

        // ---- tail: wait peers per tile, then issue next-step A loads ----
        if (t < Td - 1) {
            const __half* hn = g_hbuf[cur ^ 1];
            if (tid == 0) grp_wait(mg0, t + 1);
            __syncthreads();
            {
                const __half* h0 = hn + (size_t)mg0 * MT * Hd;
                #pragma unroll
                for (int i = 0; i < 8; i++) { int ch = acb + 4 * i; cp16(sb + SM_A0 + sA_row + (uint32_t)((ch ^ amsw) << 4), h0 + gA_row + ch * 8); }
                cp_commit();
            }
            if (tid == 0) grp_wait(mg1, t + 1);
            __syncthreads();
            {
                const __half* h1 = hn + (size_t)mg1 * MT * Hd;
                #pragma unroll
                for (int i = 0; i < 8; i++) { int ch = acb + 4 * i; cp16(sb + SM_A1 + sA_row + (uint32_t)((ch ^ amsw) << 4), h1 + gA_row + ch * 8); }
                cp_commit();
            }
        }
    }
}

// ---------------- launch ----------------
extern "C" void kernel_launch(void* const* d_in, const int* in_sizes, int n_in,
                              void* d_out, int out_size) {
    const float* x   = (const float*)d_in[0];
    const float* Wih = (const float*)d_in[1];
    const float* Whh = (const float*)d_in[2];
    const float* bih = (const float*)d_in[3];
    const float* bhh = (const float*)d_in[4];
    float* out = (float*)d_out;
    (void)in_sizes; (void)n_in; (void)out_size;

    cudaFuncSetAttribute(lstm_kernel, cudaFuncAttributeMaxDynamicSharedMemorySize, SM_TOTAL);

    prep_kernel<<<2048, 256>>>(x, Wih, Whh, bih, bhh);
    lstm_kernel<<<GRID, NTHR, SM_TOTAL>>>(out);
}

// round 12
// speedup vs baseline: 1.4075x; 1.4075x over previous
#include <cuda_runtime.h>
#include <cuda_fp16.h>
#include <cstdint>

#define DINLINE __device__ __forceinline__

static constexpr int Bd = 2048;
static constexpr int Hd = 256;
static constexpr int Td = 512;
static constexpr int MT = 64;                  // batch tile rows (per half)
static constexpr int NT = 128;                 // gate-column tile
static constexpr int NGRP = Bd / MT;           // 32 barrier groups
static constexpr int NSLC = (4 * Hd) / NT;     // 8 N-slices
static constexpr int GRID = 128;               // CTA = 2 halves (tiles) x 1 slice
static constexpr int NTHR = 256;               // 8 warps; warps 0-3 = half0, 4-7 = half1

// SMEM layout (dynamic)
static constexpr int SM_BIAS = 0;                  // 128 floats (i,f,g,o per unit)
static constexpr int SM_A0 = 1024;                 // h tile half0 [64][256] f16 swizzled (32KB)
static constexpr int SM_A1 = SM_A0 + 32768;        // h tile half1 (32KB)
static constexpr int SM_W = SM_A0 + 65536;         // W_ih [128n][256k] (64KB); W_sum at +65536
static constexpr int SM_TOTAL = SM_W + 131072;     // 197632 B

// ---------------- device globals (scratch; no allocations) ----------------
__device__ __align__(16) __half g_hbuf[2][Bd * Hd];                  // ping-pong h (fp16)
__device__ __align__(1024) unsigned char g_Wimg[2][NSLC][65536];     // [W_ih, W_ih+W_hh] smem images
__device__ float g_bias[NSLC][NT];
__device__ unsigned int g_cnt[NGRP];
__device__ int g_gen[NGRP];

// ---------------- helpers ----------------
DINLINE uint32_t smem_u32(const void* p) {
    uint32_t a;
    asm("{ .reg .u64 t; cvta.to.shared.u64 t, %1; cvt.u32.u64 %0, t; }" : "=r"(a) : "l"(p));
    return a;
}
DINLINE void cp16(uint32_t s, const void* g) {
    asm volatile("cp.async.cg.shared.global [%0], [%1], 16;" :: "r"(s), "l"(g));
}
DINLINE void cp_commit() { asm volatile("cp.async.commit_group;" ::: "memory"); }
DINLINE void cp_wait0()  { asm volatile("cp.async.wait_group 0;" ::: "memory"); }

DINLINE void barh(int id) {   // named barrier: 128 threads of one half
    asm volatile("bar.sync %0, 128;" :: "r"(id) : "memory");
}

DINLINE void ldsm4(uint32_t* r, uint32_t addr) {
    asm volatile("ldmatrix.sync.aligned.m8n8.x4.shared.b16 {%0,%1,%2,%3}, [%4];"
                 : "=r"(r[0]), "=r"(r[1]), "=r"(r[2]), "=r"(r[3]) : "r"(addr));
}
DINLINE void mma16816(float* c, const uint32_t* a, uint32_t b0, uint32_t b1) {
    asm volatile(
        "mma.sync.aligned.m16n8k16.row.col.f32.f16.f16.f32 "
        "{%0,%1,%2,%3},{%4,%5,%6,%7},{%8,%9},{%0,%1,%2,%3};"
        : "+f"(c[0]), "+f"(c[1]), "+f"(c[2]), "+f"(c[3])
        : "r"(a[0]), "r"(a[1]), "r"(a[2]), "r"(a[3]), "r"(b0), "r"(b1));
}

// single-MUFU activations (tanh.approx); recurrence damps the ~6e-4 max abs err
DINLINE float fsig(float x) {
    float t;
    asm("tanh.approx.f32 %0, %1;" : "=f"(t) : "f"(0.5f * x));
    return fmaf(0.5f, t, 0.5f);
}
DINLINE float ftanh(float x) {
    float t;
    asm("tanh.approx.f32 %0, %1;" : "=f"(t) : "f"(x));
    return t;
}

// group barrier (R2-proven): last of 8 arrivals publishes generation t+1
DINLINE void grp_release(int mg, int t) {
    unsigned old;
    asm volatile("atom.acq_rel.gpu.global.add.u32 %0, [%1], %2;"
                 : "=r"(old) : "l"(&g_cnt[mg]), "r"(1u) : "memory");
    if (old == (unsigned)(8 * (t + 1) - 1)) {
        asm volatile("st.release.gpu.global.b32 [%0], %1;" :: "l"(&g_gen[mg]), "r"(t + 1) : "memory");
    }
}
DINLINE void grp_wait(int mg, int target) {
    int v;
    do {
        asm volatile("ld.acquire.gpu.global.b32 %0, [%1];" : "=r"(v) : "l"(&g_gen[mg]) : "memory");
        if (v < target) __nanosleep(32);
    } while (v < target);
}

// ---------------- prologue: permuted/swizzled fp16 W images, bias, x->fp16 ----------------
// Column permutation within a 128-col slice: 16-col groups; w=n&15:
//   w<8:  gates (i,f)  unit = 4*(n>>4) + (w>>1), gate = w&1
//   w>=8: gates (g,o)  unit = 4*(n>>4) + ((w-8)>>1), gate = 2 + (w&1)
// -> MMA thread owning cols {2c,2c+1} of n8-tiles (2p, 2p+1) gets all 4 gates of one unit.
__global__ void prep_kernel(const float* __restrict__ x,
                            const float* __restrict__ Wih, const float* __restrict__ Whh,
                            const float* __restrict__ bih, const float* __restrict__ bhh) {
    int g = blockIdx.x * blockDim.x + threadIdx.x;
    if (g < Bd * Hd) g_hbuf[0][g] = __float2half_rn(x[g]);
    if (g < 2 * NSLC * NT * Hd) {  // 524288 entries
        int set = g >> 18;
        int r = g & 262143;
        int j = r >> 15;
        int n = (r >> 8) & 127;
        int k = r & 255;
        int w = n & 15;
        int gate = 2 * (w >> 3) + (w & 1);
        int hl = (n >> 4) * 4 + ((w >> 1) & 3);
        int row = gate * Hd + j * 32 + hl;            // original W row in (4H,H)
        float wv = Wih[row * Hd + k];
        if (set) wv += Whh[row * Hd + k];
        uint32_t byte = (uint32_t)(n * 512 + (((k >> 3) ^ (n & 7)) << 4) + (k & 7) * 2);
        *reinterpret_cast<__half*>(&g_Wimg[set][j][byte]) = __float2half_rn(wv);
    }
    if (g < NSLC * NT) {           // bias as float4 (i,f,g,o) per unit: n = unit*4+gate
        int j = g >> 7, n = g & 127;
        int gate = n & 3, hl = n >> 2;
        int row = gate * Hd + j * 32 + hl;
        g_bias[j][n] = bih[row] + bhh[row];
    }
    if (g < NGRP) { g_cnt[g] = 0; g_gen[g] = 0; }
}

// ---------------- main persistent kernel ----------------
__global__ void __launch_bounds__(NTHR, 1) lstm_kernel(float* __restrict__ out) {
    extern __shared__ __align__(1024) char smem[];
    const uint32_t sb = smem_u32(smem);
    const int tid = threadIdx.x, wid = tid >> 5, lane = tid & 31;
    const int sj = blockIdx.x & 7, cm = blockIdx.x >> 3;
    const int half = wid >> 2;                 // 0 / 1 : independent pipeline
    const int hw = wid & 3;
    const int wm = hw >> 1, wn2 = hw & 1;      // warp tile: rows wm*32, cols wn2*64
    const int htid = tid & 127;
    const int mg = cm * 2 + half;              // this half's barrier group
    const int barid = 1 + half;

    if (tid < 32)
        reinterpret_cast<float4*>(smem + SM_BIAS)[tid] = reinterpret_cast<const float4*>(g_bias[sj])[tid];
    {   // both W images resident: W_ih at SM_W, W_sum at SM_W+65536
        const unsigned char* s0 = g_Wimg[0][sj];
        const unsigned char* s1 = g_Wimg[1][sj];
        #pragma unroll
        for (int i = 0; i < 16; i++) { int q = tid + NTHR * i; cp16(sb + SM_W + q * 16, s0 + q * 16); }
        #pragma unroll
        for (int i = 0; i < 16; i++) { int q = tid + NTHR * i; cp16(sb + SM_W + 65536 + q * 16, s1 + q * 16); }
        cp_commit();
    }

    // A-tile cp.async mapping (per half): 128 threads, row = htid>>1, 16 chunks each
    const int am = htid >> 1, acb = htid & 1, amsw = am & 7;
    const uint32_t sA = sb + SM_A0 + (uint32_t)(half * 32768 + am * 512);
    const size_t gA = (size_t)(mg * MT + am) * Hd;
    {   // initial h tile for this half
        const __half* hsrc = g_hbuf[0] + gA;
        #pragma unroll
        for (int i = 0; i < 16; i++) { int ch = acb + 2 * i; cp16(sA + (uint32_t)((ch ^ amsw) << 4), hsrc + ch * 8); }
        cp_commit();
    }

    // ldmatrix per-lane address bases
    const int a_row_off = (lane & 7) + (((lane >> 3) & 1) << 3);
    const int a_ch_off  = (lane >> 4) & 1;
    uint32_t a_base[2]; int a_rsw[2];
    #pragma unroll
    for (int mt = 0; mt < 2; mt++) {
        int row = wm * 32 + mt * 16 + a_row_off;
        a_base[mt] = sb + SM_A0 + half * 32768 + row * 512;
        a_rsw[mt] = row & 7;
    }
    const int b_ch_off = (lane >> 3) & 1;
    uint32_t b_base[4]; int b_rsw[4];
    #pragma unroll
    for (int np = 0; np < 4; np++) {
        int nrow = wn2 * 64 + np * 16 + (lane & 7) + (((lane >> 4) & 1) << 3);
        b_base[np] = sb + SM_W + nrow * 512;
        b_rsw[np] = nrow & 7;
    }

    // epilogue geometry: thread rows wm*32 + (lane>>2) + {0,8,16,24}; units wn2*16 + p*4 + (lane&3)
    const int r_lane = lane >> 2, u_lane = lane & 3;
    const size_t idxb = (size_t)(mg * MT + wm * 32 + r_lane) * Hd + sj * 32;

    float cst[16];
    #pragma unroll
    for (int i = 0; i < 16; i++) cst[i] = 0.f;

    const float4* bias4 = reinterpret_cast<const float4*>(smem + SM_BIAS);

    #pragma unroll 1
    for (int t = 0; t < Td; t++) {
        const int cur = t & 1;
        const uint32_t woff = (t == 0) ? 0u : 65536u;   // W_ih at t=0, W_sum after

        // ---- A ready for this half ----
        cp_wait0();
        barh(barid);

        // ---- MMA: gates[64,128] = A[64,256] @ W[128,256]^T ----
        float acc[64];
        #pragma unroll
        for (int i = 0; i < 64; i++) acc[i] = 0.f;
        #pragma unroll
        for (int kt = 0; kt < 16; kt++) {
            uint32_t af[2][4];
            #pragma unroll
            for (int mt = 0; mt < 2; mt++)
                ldsm4(af[mt], a_base[mt] + (((2 * kt + a_ch_off) ^ a_rsw[mt]) << 4));
            uint32_t bf[4][4];
            #pragma unroll
            for (int np = 0; np < 4; np++)
                ldsm4(bf[np], b_base[np] + woff + (((2 * kt + b_ch_off) ^ b_rsw[np]) << 4));
            #pragma unroll
            for (int mt = 0; mt < 2; mt++)
                #pragma unroll
                for (int nt = 0; nt < 8; nt++)
                    mma16816(&acc[(mt * 8 + nt) * 4], af[mt],
                             bf[nt >> 1][(nt & 1) * 2], bf[nt >> 1][(nt & 1) * 2 + 1]);
        }

        // ---- epilogue: 4 gates per thread, activations, h + x_hat stores ----
        const int oidx = (t == 0) ? 0 : (Td - t);   // x_hat[0]=h0, x_hat[k]=h_{T-k}
        __half* hp = &g_hbuf[cur ^ 1][idxb];
        float* xp = out + (size_t)oidx * (Bd * Hd) + idxb;
        #pragma unroll
        for (int mt = 0; mt < 2; mt++) {
            #pragma unroll
            for (int p = 0; p < 4; p++) {
                const float* aI = &acc[(mt * 8 + 2 * p) * 4];       // (i,f) rows r0, r0+8
                const float* aG = &acc[(mt * 8 + 2 * p + 1) * 4];   // (g,o) rows r0, r0+8
                const int unit = wn2 * 16 + p * 4 + u_lane;
                float4 bb = bias4[unit];
                #pragma unroll
                for (int rh = 0; rh < 2; rh++) {
                    float iv = fsig(aI[2 * rh + 0] + bb.x);
                    float fv = fsig(aI[2 * rh + 1] + bb.y);
                    float gv = ftanh(aG[2 * rh + 0] + bb.z);
                    float ov = fsig(aG[2 * rh + 1] + bb.w);
                    const int li = mt * 8 + p * 2 + rh;
                    float cn = fmaf(fv, cst[li], iv * gv);
                    cst[li] = cn;
                    float hv = ov * ftanh(cn);
                    const size_t off = (size_t)(mt * 16 + rh * 8) * Hd + unit;
                    hp[off] = __float2half_rn(hv);
                    xp[off] = hv;
                    if (t == Td - 1) {
                        float* hfp = out + (size_t)Td * Bd * Hd + idxb;
                        hfp[off] = hv;
                        hfp[(size_t)Bd * Hd + off] = cn;
                    }
                }
            }
        }
        barh(barid);                       // half's h stores ordered before release
        if (htid == 0) grp_release(mg, t);

        // ---- wait peers of this half's group, then load next A tile ----
        if (t < Td - 1) {
            if (htid == 0) grp_wait(mg, t + 1);
            barh(barid);
            const __half* hn = g_hbuf[cur ^ 1] + gA;
            #pragma unroll
            for (int i = 0; i < 16; i++) { int ch = acb + 2 * i; cp16(sA + (uint32_t)((ch ^ amsw) << 4), hn + ch * 8); }
            cp_commit();
        }
    }
}

// ---------------- launch ----------------
extern "C" void kernel_launch(void* const* d_in, const int* in_sizes, int n_in,
                              void* d_out, int out_size) {
    const float* x   = (const float*)d_in[0];
    const float* Wih = (const float*)d_in[1];
    const float* Whh = (const float*)d_in[2];
    const float* bih = (const float*)d_in[3];
    const float* bhh = (const float*)d_in[4];
    float* out = (float*)d_out;
    (void)in_sizes; (void)n_in; (void)out_size;

    cudaFuncSetAttribute(lstm_kernel, cudaFuncAttributeMaxDynamicSharedMemorySize, SM_TOTAL);

    prep_kernel<<<2048, 256>>>(x, Wih, Whh, bih, bhh);
    lstm_kernel<<<GRID, NTHR, SM_TOTAL>>>(out);
}

// round 13
// speedup vs baseline: 1.6594x; 1.1789x over previous
#include <cuda_runtime.h>
#include <cuda_fp16.h>
#include <cstdint>

#define DINLINE __device__ __forceinline__

static constexpr int Bd = 2048;
static constexpr int Hd = 256;
static constexpr int Td = 512;
static constexpr int MT = 64;                  // batch tile rows (per half)
static constexpr int NT = 128;                 // gate-column tile
static constexpr int NGRP = Bd / MT;           // 32 barrier groups
static constexpr int NSLC = (4 * Hd) / NT;     // 8 N-slices
static constexpr int GRID = 128;               // CTA = 2 halves (tiles) x 1 slice
static constexpr int NTHR = 256;               // 8 warps; warps 0-3 = half0, 4-7 = half1

// SMEM layout (dynamic)
static constexpr int SM_BIAS = 0;                  // 128 floats (i,f,g,o per unit)
static constexpr int SM_A0 = 1024;                 // h tile half0 [64][256] f16 swizzled (32KB)
static constexpr int SM_A1 = SM_A0 + 32768;        // h tile half1 (32KB)
static constexpr int SM_W = SM_A0 + 65536;         // W_ih [128n][256k] (64KB); W_sum at +65536
static constexpr int SM_TOTAL = SM_W + 131072;     // 197632 B

// ---------------- device globals (scratch; no allocations) ----------------
__device__ __align__(16) __half g_hbuf[2][Bd * Hd];                  // ping-pong h (fp16)
__device__ __align__(1024) unsigned char g_Wimg[2][NSLC][65536];     // [W_ih, W_ih+W_hh] smem images
__device__ float g_bias[NSLC][NT];
__device__ unsigned int g_cnt[NGRP];                                 // monotonic release counters

// ---------------- helpers ----------------
DINLINE uint32_t smem_u32(const void* p) {
    uint32_t a;
    asm("{ .reg .u64 t; cvta.to.shared.u64 t, %1; cvt.u32.u64 %0, t; }" : "=r"(a) : "l"(p));
    return a;
}
DINLINE void cp16(uint32_t s, const void* g) {
    asm volatile("cp.async.cg.shared.global [%0], [%1], 16;" :: "r"(s), "l"(g));
}
DINLINE void cp_commit() { asm volatile("cp.async.commit_group;" ::: "memory"); }
DINLINE void cp_wait0()  { asm volatile("cp.async.wait_group 0;" ::: "memory"); }
DINLINE void cp_wait1()  { asm volatile("cp.async.wait_group 1;" ::: "memory"); }

DINLINE void barh(int id) {   // named barrier: 128 threads of one half
    asm volatile("bar.sync %0, 128;" :: "r"(id) : "memory");
}

DINLINE void ldsm4(uint32_t* r, uint32_t addr) {
    asm volatile("ldmatrix.sync.aligned.m8n8.x4.shared.b16 {%0,%1,%2,%3}, [%4];"
                 : "=r"(r[0]), "=r"(r[1]), "=r"(r[2]), "=r"(r[3]) : "r"(addr));
}
DINLINE void mma16816(float* c, const uint32_t* a, uint32_t b0, uint32_t b1) {
    asm volatile(
        "mma.sync.aligned.m16n8k16.row.col.f32.f16.f16.f32 "
        "{%0,%1,%2,%3},{%4,%5,%6,%7},{%8,%9},{%0,%1,%2,%3};"
        : "+f"(c[0]), "+f"(c[1]), "+f"(c[2]), "+f"(c[3])
        : "r"(a[0]), "r"(a[1]), "r"(a[2]), "r"(a[3]), "r"(b0), "r"(b1));
}

// single-MUFU activations (tanh.approx); recurrence damps the approx noise
DINLINE float fsig(float x) {
    float t;
    asm("tanh.approx.f32 %0, %1;" : "=f"(t) : "f"(0.5f * x));
    return fmaf(0.5f, t, 0.5f);
}
DINLINE float ftanh(float x) {
    float t;
    asm("tanh.approx.f32 %0, %1;" : "=f"(t) : "f"(x));
    return t;
}

// group barrier: fire-and-forget release; waiter polls the monotonic counter
DINLINE void grp_release(int mg) {
    asm volatile("red.release.gpu.global.add.u32 [%0], %1;" :: "l"(&g_cnt[mg]), "r"(1u) : "memory");
}
DINLINE void grp_wait(int mg, unsigned target) {
    unsigned v;
    do {
        asm volatile("ld.acquire.gpu.global.u32 %0, [%1];" : "=r"(v) : "l"(&g_cnt[mg]) : "memory");
    } while (v < target);
}

// ---------------- prologue: permuted/swizzled fp16 W images, bias, x->fp16 ----------------
// Column permutation within a 128-col slice: 16-col groups; w=n&15:
//   w<8:  gates (i,f)  unit = 4*(n>>4) + (w>>1), gate = w&1
//   w>=8: gates (g,o)  unit = 4*(n>>4) + ((w-8)>>1), gate = 2 + (w&1)
// -> MMA thread owning cols {2c,2c+1} of n8-tiles (2p, 2p+1) gets all 4 gates of one unit.
__global__ void prep_kernel(const float* __restrict__ x,
                            const float* __restrict__ Wih, const float* __restrict__ Whh,
                            const float* __restrict__ bih, const float* __restrict__ bhh) {
    int g = blockIdx.x * blockDim.x + threadIdx.x;
    if (g < Bd * Hd) g_hbuf[0][g] = __float2half_rn(x[g]);
    if (g < 2 * NSLC * NT * Hd) {  // 524288 entries
        int set = g >> 18;
        int r = g & 262143;
        int j = r >> 15;
        int n = (r >> 8) & 127;
        int k = r & 255;
        int w = n & 15;
        int gate = 2 * (w >> 3) + (w & 1);
        int hl = (n >> 4) * 4 + ((w >> 1) & 3);
        int row = gate * Hd + j * 32 + hl;            // original W row in (4H,H)
        float wv = Wih[row * Hd + k];
        if (set) wv += Whh[row * Hd + k];
        uint32_t byte = (uint32_t)(n * 512 + (((k >> 3) ^ (n & 7)) << 4) + (k & 7) * 2);
        *reinterpret_cast<__half*>(&g_Wimg[set][j][byte]) = __float2half_rn(wv);
    }
    if (g < NSLC * NT) {           // bias as float4 (i,f,g,o) per unit: n = unit*4+gate
        int j = g >> 7, n = g & 127;
        int gate = n & 3, hl = n >> 2;
        int row = gate * Hd + j * 32 + hl;
        g_bias[j][n] = bih[row] + bhh[row];
    }
    if (g < NGRP) g_cnt[g] = 0;
}

// ---------------- main persistent kernel ----------------
__global__ void __launch_bounds__(NTHR, 1) lstm_kernel(float* __restrict__ out) {
    extern __shared__ __align__(1024) char smem[];
    const uint32_t sb = smem_u32(smem);
    const int tid = threadIdx.x, wid = tid >> 5, lane = tid & 31;
    const int sj = blockIdx.x & 7, cm = blockIdx.x >> 3;
    const int half = wid >> 2;                 // 0 / 1 : independent pipeline
    const int hw = wid & 3;
    const int wm = hw >> 1, wn2 = hw & 1;      // warp tile: rows wm*32, cols wn2*64
    const int htid = tid & 127;
    const int mg = cm * 2 + half;              // this half's barrier group
    const int barid = 1 + half;

    if (tid < 32)
        reinterpret_cast<float4*>(smem + SM_BIAS)[tid] = reinterpret_cast<const float4*>(g_bias[sj])[tid];
    {   // both W images resident: W_ih at SM_W, W_sum at +65536
        const unsigned char* s0 = g_Wimg[0][sj];
        const unsigned char* s1 = g_Wimg[1][sj];
        #pragma unroll
        for (int i = 0; i < 16; i++) { int q = tid + NTHR * i; cp16(sb + SM_W + q * 16, s0 + q * 16); }
        #pragma unroll
        for (int i = 0; i < 16; i++) { int q = tid + NTHR * i; cp16(sb + SM_W + 65536 + q * 16, s1 + q * 16); }
    }

    // A-tile cp.async mapping (per half): 128 threads, row = htid>>1, 16 chunks each
    const int am = htid >> 1, acb = htid & 1, amsw = am & 7;
    const uint32_t sA = sb + SM_A0 + (uint32_t)(half * 32768 + am * 512);
    const size_t gA = (size_t)(mg * MT + am) * Hd;
    {   // initial h tile for this half
        const __half* hsrc = g_hbuf[0] + gA;
        #pragma unroll
        for (int i = 0; i < 16; i++) { int ch = acb + 2 * i; cp16(sA + (uint32_t)((ch ^ amsw) << 4), hsrc + ch * 8); }
    }
    cp_commit();
    cp_wait0();
    __syncthreads();   // W / bias / initial A visible CTA-wide (fixes cross-half visibility)

    // one-time anti-phase skew for half1: its pipeline runs ~half a step behind half0,
    // so each half's MMA covers the other's barrier+load window. Cadence preserves the offset.
    if (half == 1) {
        unsigned long long c0 = clock64();
        while (clock64() - c0 < 4000ull) { }
    }

    // ldmatrix per-lane address bases
    const int a_row_off = (lane & 7) + (((lane >> 3) & 1) << 3);
    const int a_ch_off  = (lane >> 4) & 1;
    uint32_t a_base[2]; int a_rsw[2];
    #pragma unroll
    for (int mt = 0; mt < 2; mt++) {
        int row = wm * 32 + mt * 16 + a_row_off;
        a_base[mt] = sb + SM_A0 + half * 32768 + row * 512;
        a_rsw[mt] = row & 7;
    }
    const int b_ch_off = (lane >> 3) & 1;
    uint32_t b_base[4]; int b_rsw[4];
    #pragma unroll
    for (int np = 0; np < 4; np++) {
        int nrow = wn2 * 64 + np * 16 + (lane & 7) + (((lane >> 4) & 1) << 3);
        b_base[np] = sb + SM_W + nrow * 512;
        b_rsw[np] = nrow & 7;
    }

    // epilogue geometry: thread rows wm*32 + (lane>>2) + {0,8,16,24}; units wn2*16 + p*4 + (lane&3)
    const int r_lane = lane >> 2, u_lane = lane & 3;
    const size_t idxb = (size_t)(mg * MT + wm * 32 + r_lane) * Hd + sj * 32;

    float cst[16];
    #pragma unroll
    for (int i = 0; i < 16; i++) cst[i] = 0.f;

    const float4* bias4 = reinterpret_cast<const float4*>(smem + SM_BIAS);

    #pragma unroll 1
    for (int t = 0; t < Td; t++) {
        const int cur = t & 1;
        const uint32_t woff = (t == 0) ? 0u : 65536u;   // W_ih at t=0, W_sum after

        float acc[64];
        #pragma unroll
        for (int i = 0; i < 64; i++) acc[i] = 0.f;

        // ---- K-half 0 ready -> MMA kt 0..7 while K-half 1 streams in ----
        cp_wait1();          // t=0: no pending groups, passes immediately
        barh(barid);
        #pragma unroll
        for (int kt = 0; kt < 8; kt++) {
            uint32_t af[2][4];
            #pragma unroll
            for (int mt = 0; mt < 2; mt++)
                ldsm4(af[mt], a_base[mt] + (((2 * kt + a_ch_off) ^ a_rsw[mt]) << 4));
            uint32_t bf[4][4];
            #pragma unroll
            for (int np = 0; np < 4; np++)
                ldsm4(bf[np], b_base[np] + woff + (((2 * kt + b_ch_off) ^ b_rsw[np]) << 4));
            #pragma unroll
            for (int mt = 0; mt < 2; mt++)
                #pragma unroll
                for (int nt = 0; nt < 8; nt++)
                    mma16816(&acc[(mt * 8 + nt) * 4], af[mt],
                             bf[nt >> 1][(nt & 1) * 2], bf[nt >> 1][(nt & 1) * 2 + 1]);
        }
        cp_wait0();
        barh(barid);
        #pragma unroll
        for (int kt = 8; kt < 16; kt++) {
            uint32_t af[2][4];
            #pragma unroll
            for (int mt = 0; mt < 2; mt++)
                ldsm4(af[mt], a_base[mt] + (((2 * kt + a_ch_off) ^ a_rsw[mt]) << 4));
            uint32_t bf[4][4];
            #pragma unroll
            for (int np = 0; np < 4; np++)
                ldsm4(bf[np], b_base[np] + woff + (((2 * kt + b_ch_off) ^ b_rsw[np]) << 4));
            #pragma unroll
            for (int mt = 0; mt < 2; mt++)
                #pragma unroll
                for (int nt = 0; nt < 8; nt++)
                    mma16816(&acc[(mt * 8 + nt) * 4], af[mt],
                             bf[nt >> 1][(nt & 1) * 2], bf[nt >> 1][(nt & 1) * 2 + 1]);
        }

        // ---- epilogue: 4 gates per thread, activations, h stores (critical path) ----
        const int oidx = (t == 0) ? 0 : (Td - t);   // x_hat[0]=h0, x_hat[k]=h_{T-k}
        __half* hp = &g_hbuf[cur ^ 1][idxb];
        float hvr[16];
        #pragma unroll
        for (int mt = 0; mt < 2; mt++) {
            #pragma unroll
            for (int p = 0; p < 4; p++) {
                const float* aI = &acc[(mt * 8 + 2 * p) * 4];       // (i,f) rows r0, r0+8
                const float* aG = &acc[(mt * 8 + 2 * p + 1) * 4];   // (g,o) rows r0, r0+8
                const int unit = wn2 * 16 + p * 4 + u_lane;
                float4 bb = bias4[unit];
                #pragma unroll
                for (int rh = 0; rh < 2; rh++) {
                    float iv = fsig(aI[2 * rh + 0] + bb.x);
                    float fv = fsig(aI[2 * rh + 1] + bb.y);
                    float gv = ftanh(aG[2 * rh + 0] + bb.z);
                    float ov = fsig(aG[2 * rh + 1] + bb.w);
                    const int li = mt * 8 + p * 2 + rh;
                    float cn = fmaf(fv, cst[li], iv * gv);
                    cst[li] = cn;
                    float hv = ov * ftanh(cn);
                    hvr[li] = hv;
                    hp[(size_t)(mt * 16 + rh * 8) * Hd + unit] = __float2half_rn(hv);
                }
            }
        }
        barh(barid);                       // half's h stores ordered before release
        if (htid == 0) grp_release(mg);

        // ---- deferred x_hat (and final hf/cf) stores: fill the wait window ----
        float* xp = out + (size_t)oidx * (Bd * Hd) + idxb;
        #pragma unroll
        for (int mt = 0; mt < 2; mt++)
            #pragma unroll
            for (int p = 0; p < 4; p++) {
                const int unit = wn2 * 16 + p * 4 + u_lane;
                #pragma unroll
                for (int rh = 0; rh < 2; rh++)
                    xp[(size_t)(mt * 16 + rh * 8) * Hd + unit] = hvr[mt * 8 + p * 2 + rh];
            }
        if (t == Td - 1) {
            float* hfp = out + (size_t)Td * Bd * Hd + idxb;
            #pragma unroll
            for (int mt = 0; mt < 2; mt++)
                #pragma unroll
                for (int p = 0; p < 4; p++) {
                    const int unit = wn2 * 16 + p * 4 + u_lane;
                    #pragma unroll
                    for (int rh = 0; rh < 2; rh++) {
                        const int li = mt * 8 + p * 2 + rh;
                        const size_t off = (size_t)(mt * 16 + rh * 8) * Hd + unit;
                        hfp[off] = hvr[li];
                        hfp[(size_t)Bd * Hd + off] = cst[li];
                    }
                }
        }

        // ---- wait peers of this half's group, then load next A tile (two K-half groups) ----
        if (t < Td - 1) {
            if (htid == 0) grp_wait(mg, (unsigned)(8 * (t + 1)));
            barh(barid);
            const __half* hn = g_hbuf[cur ^ 1] + gA;
            #pragma unroll
            for (int i = 0; i < 8; i++) { int ch = acb + 2 * i; cp16(sA + (uint32_t)((ch ^ amsw) << 4), hn + ch * 8); }
            cp_commit();
            #pragma unroll
            for (int i = 8; i < 16; i++) { int ch = acb + 2 * i; cp16(sA + (uint32_t)((ch ^ amsw) << 4), hn + ch * 8); }
            cp_commit();
        }
    }
}

// ---------------- launch ----------------
extern "C" void kernel_launch(void* const* d_in, const int* in_sizes, int n_in,
                              void* d_out, int out_size) {
    const float* x   = (const float*)d_in[0];
    const float* Wih = (const float*)d_in[1];
    const float* Whh = (const float*)d_in[2];
    const float* bih = (const float*)d_in[3];
    const float* bhh = (const float*)d_in[4];
    float* out = (float*)d_out;
    (void)in_sizes; (void)n_in; (void)out_size;

    cudaFuncSetAttribute(lstm_kernel, cudaFuncAttributeMaxDynamicSharedMemorySize, SM_TOTAL);

    prep_kernel<<<2048, 256>>>(x, Wih, Whh, bih, bhh);
    lstm_kernel<<<GRID, NTHR, SM_TOTAL>>>(out);
}